// round 2
// baseline (speedup 1.0000x reference)
#include <cuda_runtime.h>
#include <math.h>

#define B_SZ 512
#define T_SZ 256
#define F_SZ 1024

// Scratch (allocation-free rule: __device__ globals)
__device__ float g_q[B_SZ * F_SZ];
__device__ float g_qk[B_SZ * F_SZ];
__device__ float g_ctxf[B_SZ * F_SZ];

// ---------------------------------------------------------------------------
// SGEMM NT: C[m,n] = sum_k A[m,k] * B[n,k] (+ bias[n])
// A: [M,K] row-major, Bm: [N,K] row-major. M,N mult of 64, K mult of 16.
// ---------------------------------------------------------------------------
template <bool HAS_BIAS>
__global__ __launch_bounds__(256) void sgemm_nt(const float* __restrict__ A,
                                                const float* __restrict__ Bm,
                                                const float* __restrict__ bias,
                                                float* __restrict__ C,
                                                int M, int N, int K)
{
    __shared__ float As[16][64];
    __shared__ float Bs[16][64];

    const int bm = blockIdx.y * 64;
    const int bn = blockIdx.x * 64;
    const int tid = threadIdx.x;
    const int lrow = tid >> 2;           // 0..63
    const int lk   = (tid & 3) * 4;      // 0,4,8,12
    const int ty = tid >> 4;             // 0..15
    const int tx = tid & 15;             // 0..15

    float acc[4][4] = {};

    for (int k0 = 0; k0 < K; k0 += 16) {
        float4 a = *(const float4*)&A [(size_t)(bm + lrow) * K + k0 + lk];
        float4 b = *(const float4*)&Bm[(size_t)(bn + lrow) * K + k0 + lk];
        As[lk + 0][lrow] = a.x; As[lk + 1][lrow] = a.y;
        As[lk + 2][lrow] = a.z; As[lk + 3][lrow] = a.w;
        Bs[lk + 0][lrow] = b.x; Bs[lk + 1][lrow] = b.y;
        Bs[lk + 2][lrow] = b.z; Bs[lk + 3][lrow] = b.w;
        __syncthreads();

        #pragma unroll
        for (int kk = 0; kk < 16; kk++) {
            float4 av = *(const float4*)&As[kk][ty * 4];
            float4 bv = *(const float4*)&Bs[kk][tx * 4];
            float ar[4] = {av.x, av.y, av.z, av.w};
            float br[4] = {bv.x, bv.y, bv.z, bv.w};
            #pragma unroll
            for (int i = 0; i < 4; i++)
                #pragma unroll
                for (int j = 0; j < 4; j++)
                    acc[i][j] += ar[i] * br[j];
        }
        __syncthreads();
    }

    #pragma unroll
    for (int i = 0; i < 4; i++) {
        float4 o;
        int n = bn + tx * 4;
        o.x = acc[i][0]; o.y = acc[i][1]; o.z = acc[i][2]; o.w = acc[i][3];
        if (HAS_BIAS) {
            float4 bb = *(const float4*)&bias[n];
            o.x += bb.x; o.y += bb.y; o.z += bb.z; o.w += bb.w;
        }
        *(float4*)&C[(size_t)(bm + ty * 4 + i) * N + n] = o;
    }
}

// ---------------------------------------------------------------------------
// SGEMM NN: C[m,n] = sum_k A[m,k] * B[k,n]
// A: [M,K] row-major, Bm: [K,N] row-major.
// ---------------------------------------------------------------------------
__global__ __launch_bounds__(256) void sgemm_nn(const float* __restrict__ A,
                                                const float* __restrict__ Bm,
                                                float* __restrict__ C,
                                                int M, int N, int K)
{
    __shared__ float As[16][64];
    __shared__ float Bs[16][64];

    const int bm = blockIdx.y * 64;
    const int bn = blockIdx.x * 64;
    const int tid = threadIdx.x;
    const int lrow = tid >> 2;
    const int lk   = (tid & 3) * 4;
    const int krow = tid >> 4;           // 0..15
    const int nq   = (tid & 15) * 4;     // 0..60
    const int ty = tid >> 4;
    const int tx = tid & 15;

    float acc[4][4] = {};

    for (int k0 = 0; k0 < K; k0 += 16) {
        float4 a = *(const float4*)&A [(size_t)(bm + lrow) * K + k0 + lk];
        float4 b = *(const float4*)&Bm[(size_t)(k0 + krow) * N + bn + nq];
        As[lk + 0][lrow] = a.x; As[lk + 1][lrow] = a.y;
        As[lk + 2][lrow] = a.z; As[lk + 3][lrow] = a.w;
        *(float4*)&Bs[krow][nq] = b;
        __syncthreads();

        #pragma unroll
        for (int kk = 0; kk < 16; kk++) {
            float4 av = *(const float4*)&As[kk][ty * 4];
            float4 bv = *(const float4*)&Bs[kk][tx * 4];
            float ar[4] = {av.x, av.y, av.z, av.w};
            float br[4] = {bv.x, bv.y, bv.z, bv.w};
            #pragma unroll
            for (int i = 0; i < 4; i++)
                #pragma unroll
                for (int j = 0; j < 4; j++)
                    acc[i][j] += ar[i] * br[j];
        }
        __syncthreads();
    }

    #pragma unroll
    for (int i = 0; i < 4; i++) {
        float4 o;
        o.x = acc[i][0]; o.y = acc[i][1]; o.z = acc[i][2]; o.w = acc[i][3];
        *(float4*)&C[(size_t)(bm + ty * 4 + i) * N + bn + tx * 4] = o;
    }
}

// ---------------------------------------------------------------------------
// Fused attention stream: per batch row b,
//   scores[t] = sum_f x[b,t,f]*qk[b,f]; online softmax;
//   ctxf[b,f] = sum_t softmax(scores)[t] * x[b,t,f]
// One CTA per b, 256 threads, 8-row T tiles in SMEM. Single pass over x.
// ---------------------------------------------------------------------------
__global__ __launch_bounds__(256) void attn_stream(const float* __restrict__ x,
                                                   const float* __restrict__ qk,
                                                   float* __restrict__ ctxf)
{
    const int b = blockIdx.x;
    const int tid = threadIdx.x;
    const int w = tid >> 5;   // warp id 0..7 -> handles row t = w in tile
    const int l = tid & 31;

    __shared__ float4 qk4s[256];       // 4 KB
    __shared__ float4 tile[8 * 256];   // 32 KB  (8 T-rows x 1024 floats)
    __shared__ float  s_tile[8];

    qk4s[tid] = ((const float4*)(qk + (size_t)b * F_SZ))[tid];
    const float4* x4 = (const float4*)(x + (size_t)b * T_SZ * F_SZ);

    float m = -INFINITY, Z = 0.0f;
    float4 acc = make_float4(0.f, 0.f, 0.f, 0.f);

    for (int t0 = 0; t0 < T_SZ; t0 += 8) {
        __syncthreads();   // qk4s ready (iter 0); tile/s_tile consumers done (iter>0)

        // load 8 rows (2048 float4) coalesced
        #pragma unroll
        for (int i = 0; i < 8; i++)
            tile[i * 256 + tid] = x4[(size_t)(t0 + i) * 256 + tid];
        __syncthreads();

        // scores: warp w computes dot(x[t0+w,:], qk[b,:])
        {
            float p = 0.f;
            #pragma unroll
            for (int k = 0; k < 8; k++) {
                float4 xv = tile[w * 256 + l + 32 * k];
                float4 qv = qk4s[l + 32 * k];
                p += xv.x * qv.x + xv.y * qv.y + xv.z * qv.z + xv.w * qv.w;
            }
            #pragma unroll
            for (int off = 16; off; off >>= 1)
                p += __shfl_down_sync(0xffffffffu, p, off);
            if (l == 0) s_tile[w] = p;
        }
        __syncthreads();

        // online softmax update (redundant across threads, deterministic)
        float tm = s_tile[0];
        #pragma unroll
        for (int t = 1; t < 8; t++) tm = fmaxf(tm, s_tile[t]);
        float m_new = fmaxf(m, tm);
        float scale = __expf(m - m_new);   // exp(-inf)=0 on first tile
        Z *= scale;
        acc.x *= scale; acc.y *= scale; acc.z *= scale; acc.w *= scale;

        #pragma unroll
        for (int t = 0; t < 8; t++) {
            float wt = __expf(s_tile[t] - m_new);
            Z += wt;
            float4 xv = tile[t * 256 + tid];
            acc.x += wt * xv.x; acc.y += wt * xv.y;
            acc.z += wt * xv.z; acc.w += wt * xv.w;
        }
        m = m_new;
    }

    float inv = 1.0f / Z;
    float4 o = make_float4(acc.x * inv, acc.y * inv, acc.z * inv, acc.w * inv);
    ((float4*)(ctxf + (size_t)b * F_SZ))[tid] = o;
}

// ---------------------------------------------------------------------------
extern "C" void kernel_launch(void* const* d_in, const int* in_sizes, int n_in,
                              void* d_out, int out_size)
{
    const float* z  = (const float*)d_in[0];   // [B,F]
    const float* x  = (const float*)d_in[1];   // [B,T,F]
    const float* Wq = (const float*)d_in[2];   // [D,F]
    const float* Wk = (const float*)d_in[3];   // [D,F]
    const float* Wv = (const float*)d_in[4];   // [D,F]
    const float* bq = (const float*)d_in[5];   // [D]
    // d_in[6] = bk: softmax-invariant (constant shift per row) -> dropped
    const float* bv = (const float*)d_in[7];   // [D]
    float* out = (float*)d_out;                // [B,D]

    float *q, *qkp, *ctxf;
    cudaGetSymbolAddress((void**)&q,    g_q);
    cudaGetSymbolAddress((void**)&qkp,  g_qk);
    cudaGetSymbolAddress((void**)&ctxf, g_ctxf);

    dim3 gemm_grid(F_SZ / 64, B_SZ / 64);   // (16, 8)

    // 1. q = z @ Wq^T + bq
    sgemm_nt<true><<<gemm_grid, 256>>>(z, Wq, bq, q, B_SZ, F_SZ, F_SZ);
    // 2. qk = q @ Wk   (contraction over first index of Wk[d,f])
    sgemm_nn<<<gemm_grid, 256>>>(q, Wk, qkp, B_SZ, F_SZ, F_SZ);
    // 3. fused scores + softmax + weighted-input accumulation
    attn_stream<<<B_SZ, 256>>>(x, qkp, ctxf);
    // 4. out = ctxf @ Wv^T + bv
    sgemm_nt<true><<<gemm_grid, 256>>>(ctxf, Wv, bv, out, B_SZ, F_SZ, F_SZ);
}

// round 3
// speedup vs baseline: 1.3132x; 1.3132x over previous
#include <cuda_runtime.h>
#include <math.h>

#define B_SZ 512
#define T_SZ 256
#define F_SZ 1024
#define SPLITK 4
#define KSLICE (F_SZ / SPLITK)   // 256
#define BK 16
#define NTILES (KSLICE / BK)     // 16

// Scratch (allocation-free rule: __device__ globals)
__device__ float g_q[B_SZ * F_SZ];
__device__ float g_qk[B_SZ * F_SZ];
__device__ float g_ctxf[B_SZ * F_SZ];
__device__ float g_part[SPLITK * B_SZ * F_SZ];

typedef unsigned long long u64;

__device__ __forceinline__ u64 pack_dup(float a) {
    u64 r;
    unsigned int ai = __float_as_uint(a);
    asm("mov.b64 %0, {%1, %1};" : "=l"(r) : "r"(ai));
    return r;
}
__device__ __forceinline__ void ffma2(u64& d, u64 a, u64 b) {
    asm("fma.rn.f32x2 %0, %1, %2, %0;" : "+l"(d) : "l"(a), "l"(b));
}
__device__ __forceinline__ float2 u64_f2(u64 v) {
    float2 f;
    f.x = __uint_as_float((unsigned int)v);
    f.y = __uint_as_float((unsigned int)(v >> 32));
    return f;
}

// ---------------------------------------------------------------------------
// Split-K SGEMM, M=512, N=1024, K=1024 hardcoded.
// B_IS_NT: B is [N,K] row-major (C = A @ B^T). else B is [K,N] (C = A @ B).
// Writes partial sums: Cpart[s][m][n] for K-slice s.
// 64x64 block tile, BK=16, 256 threads, 4x4 micro-tile via fp32x2 FMA,
// double-buffered SMEM with register prefetch.
// ---------------------------------------------------------------------------
template <bool B_IS_NT>
__global__ __launch_bounds__(256) void sgemm_splitk(const float* __restrict__ A,
                                                    const float* __restrict__ Bm,
                                                    float* __restrict__ Cpart)
{
    __shared__ float As[2][BK][64];
    __shared__ float Bs[2][BK][64];

    const int bm = blockIdx.y * 64;
    const int bn = blockIdx.x * 64;
    const int s  = blockIdx.z;
    const int k0 = s * KSLICE;
    const int tid = threadIdx.x;
    const int lrow = tid >> 2;           // 0..63
    const int lk   = (tid & 3) * 4;      // 0,4,8,12
    const int krow = tid >> 4;           // 0..15 (NN B load)
    const int nq   = (tid & 15) * 4;     // 0..60 (NN B load)
    const int ty = tid >> 4;             // 0..15
    const int tx = tid & 15;             // 0..15

    const float* Ap = A + (size_t)(bm + lrow) * F_SZ + k0 + lk;
    const float* Bp = B_IS_NT ? Bm + (size_t)(bn + lrow) * F_SZ + k0 + lk
                              : Bm + (size_t)(k0 + krow) * F_SZ + bn + nq;

    float4 ra = *(const float4*)Ap;
    float4 rb = *(const float4*)Bp;

    u64 acc[4][2];
    #pragma unroll
    for (int i = 0; i < 4; i++) { acc[i][0] = 0ull; acc[i][1] = 0ull; }

    // stage tile 0
    As[0][lk + 0][lrow] = ra.x; As[0][lk + 1][lrow] = ra.y;
    As[0][lk + 2][lrow] = ra.z; As[0][lk + 3][lrow] = ra.w;
    if (B_IS_NT) {
        Bs[0][lk + 0][lrow] = rb.x; Bs[0][lk + 1][lrow] = rb.y;
        Bs[0][lk + 2][lrow] = rb.z; Bs[0][lk + 3][lrow] = rb.w;
    } else {
        *(float4*)&Bs[0][krow][nq] = rb;
    }
    __syncthreads();

    int buf = 0;
    for (int kt = 0; kt < NTILES; kt++) {
        if (kt + 1 < NTILES) {                       // prefetch next tile to regs
            ra = *(const float4*)(Ap + (kt + 1) * BK);
            rb = B_IS_NT ? *(const float4*)(Bp + (kt + 1) * BK)
                         : *(const float4*)(Bp + (size_t)(kt + 1) * BK * F_SZ);
        }

        #pragma unroll
        for (int kk = 0; kk < BK; kk++) {
            float4 av = *(const float4*)&As[buf][kk][ty * 4];
            ulonglong2 bv = *(const ulonglong2*)&Bs[buf][kk][tx * 4];
            u64 a0 = pack_dup(av.x), a1 = pack_dup(av.y);
            u64 a2 = pack_dup(av.z), a3 = pack_dup(av.w);
            ffma2(acc[0][0], a0, bv.x); ffma2(acc[0][1], a0, bv.y);
            ffma2(acc[1][0], a1, bv.x); ffma2(acc[1][1], a1, bv.y);
            ffma2(acc[2][0], a2, bv.x); ffma2(acc[2][1], a2, bv.y);
            ffma2(acc[3][0], a3, bv.x); ffma2(acc[3][1], a3, bv.y);
        }

        if (kt + 1 < NTILES) {
            int nb = buf ^ 1;
            As[nb][lk + 0][lrow] = ra.x; As[nb][lk + 1][lrow] = ra.y;
            As[nb][lk + 2][lrow] = ra.z; As[nb][lk + 3][lrow] = ra.w;
            if (B_IS_NT) {
                Bs[nb][lk + 0][lrow] = rb.x; Bs[nb][lk + 1][lrow] = rb.y;
                Bs[nb][lk + 2][lrow] = rb.z; Bs[nb][lk + 3][lrow] = rb.w;
            } else {
                *(float4*)&Bs[nb][krow][nq] = rb;
            }
            __syncthreads();
            buf = nb;
        }
    }

    float* Cp = Cpart + (size_t)s * (B_SZ * F_SZ)
                      + (size_t)(bm + ty * 4) * F_SZ + bn + tx * 4;
    #pragma unroll
    for (int i = 0; i < 4; i++) {
        float2 p0 = u64_f2(acc[i][0]);
        float2 p1 = u64_f2(acc[i][1]);
        float4 o = make_float4(p0.x, p0.y, p1.x, p1.y);
        *(float4*)(Cp + (size_t)i * F_SZ) = o;
    }
}

// ---------------------------------------------------------------------------
// Reduce SPLITK partials (+ optional bias broadcast over rows).
// One float4 per thread. grid = B*F/4/256 = 512 blocks.
// ---------------------------------------------------------------------------
template <bool HAS_BIAS>
__global__ __launch_bounds__(256) void reduce_k(const float* __restrict__ part,
                                                const float* __restrict__ bias,
                                                float* __restrict__ out)
{
    const int idx = blockIdx.x * 256 + threadIdx.x;      // float4 index
    const int Q = B_SZ * F_SZ / 4;
    const float4* p = (const float4*)part;
    float4 a = p[idx];
    float4 b = p[idx + Q];
    float4 c = p[idx + 2 * Q];
    float4 d = p[idx + 3 * Q];
    float4 o;
    o.x = (a.x + b.x) + (c.x + d.x);
    o.y = (a.y + b.y) + (c.y + d.y);
    o.z = (a.z + b.z) + (c.z + d.z);
    o.w = (a.w + b.w) + (c.w + d.w);
    if (HAS_BIAS) {
        float4 bb = ((const float4*)bias)[idx & (F_SZ / 4 - 1)];
        o.x += bb.x; o.y += bb.y; o.z += bb.z; o.w += bb.w;
    }
    ((float4*)out)[idx] = o;
}

// ---------------------------------------------------------------------------
// Fused attention stream with register prefetch of the next 8-row tile:
//   scores[t] = sum_f x[b,t,f]*qk[b,f]; online softmax;
//   ctxf[b,f] = sum_t softmax(scores)[t] * x[b,t,f]
// ---------------------------------------------------------------------------
__global__ __launch_bounds__(256) void attn_stream(const float* __restrict__ x,
                                                   const float* __restrict__ qk,
                                                   float* __restrict__ ctxf)
{
    const int b = blockIdx.x;
    const int tid = threadIdx.x;
    const int w = tid >> 5;   // warp id 0..7 -> row t = t0 + w
    const int l = tid & 31;

    __shared__ float4 qk4s[256];       // 4 KB
    __shared__ float4 tile[8 * 256];   // 32 KB  (8 T-rows x 1024 floats)
    __shared__ float  s_tile[8];

    qk4s[tid] = ((const float4*)(qk + (size_t)b * F_SZ))[tid];
    const float4* x4 = (const float4*)(x + (size_t)b * T_SZ * F_SZ);

    float4 r[8];
    #pragma unroll
    for (int i = 0; i < 8; i++) r[i] = x4[(size_t)i * 256 + tid];

    float m = -INFINITY, Z = 0.0f;
    float4 acc = make_float4(0.f, 0.f, 0.f, 0.f);

    for (int t0 = 0; t0 < T_SZ; t0 += 8) {
        __syncthreads();   // prior tile consumers done; qk4s ready (iter 0)

        #pragma unroll
        for (int i = 0; i < 8; i++) tile[i * 256 + tid] = r[i];
        __syncthreads();

        if (t0 + 8 < T_SZ) {           // prefetch next tile (overlaps compute)
            #pragma unroll
            for (int i = 0; i < 8; i++)
                r[i] = x4[(size_t)(t0 + 8 + i) * 256 + tid];
        }

        // scores: warp w computes dot(x[t0+w,:], qk[b,:])
        {
            float p = 0.f;
            #pragma unroll
            for (int k = 0; k < 8; k++) {
                float4 xv = tile[w * 256 + l + 32 * k];
                float4 qv = qk4s[l + 32 * k];
                p += xv.x * qv.x + xv.y * qv.y + xv.z * qv.z + xv.w * qv.w;
            }
            #pragma unroll
            for (int off = 16; off; off >>= 1)
                p += __shfl_down_sync(0xffffffffu, p, off);
            if (l == 0) s_tile[w] = p;
        }
        __syncthreads();

        // online softmax update (redundant across threads, deterministic)
        float tm = s_tile[0];
        #pragma unroll
        for (int t = 1; t < 8; t++) tm = fmaxf(tm, s_tile[t]);
        float m_new = fmaxf(m, tm);
        float scale = __expf(m - m_new);   // exp(-inf)=0 on first tile
        Z *= scale;
        acc.x *= scale; acc.y *= scale; acc.z *= scale; acc.w *= scale;

        #pragma unroll
        for (int t = 0; t < 8; t++) {
            float wt = __expf(s_tile[t] - m_new);
            Z += wt;
            float4 xv = tile[t * 256 + tid];
            acc.x += wt * xv.x; acc.y += wt * xv.y;
            acc.z += wt * xv.z; acc.w += wt * xv.w;
        }
        m = m_new;
    }

    float inv = 1.0f / Z;
    float4 o = make_float4(acc.x * inv, acc.y * inv, acc.z * inv, acc.w * inv);
    ((float4*)(ctxf + (size_t)b * F_SZ))[tid] = o;
}

// ---------------------------------------------------------------------------
extern "C" void kernel_launch(void* const* d_in, const int* in_sizes, int n_in,
                              void* d_out, int out_size)
{
    const float* z  = (const float*)d_in[0];   // [B,F]
    const float* x  = (const float*)d_in[1];   // [B,T,F]
    const float* Wq = (const float*)d_in[2];   // [D,F]
    const float* Wk = (const float*)d_in[3];   // [D,F]
    const float* Wv = (const float*)d_in[4];   // [D,F]
    const float* bq = (const float*)d_in[5];   // [D]
    // d_in[6] = bk: softmax-invariant (constant shift per row) -> dropped
    const float* bv = (const float*)d_in[7];   // [D]
    float* out = (float*)d_out;                // [B,D]

    float *q, *qkp, *ctxf, *part;
    cudaGetSymbolAddress((void**)&q,    g_q);
    cudaGetSymbolAddress((void**)&qkp,  g_qk);
    cudaGetSymbolAddress((void**)&ctxf, g_ctxf);
    cudaGetSymbolAddress((void**)&part, g_part);

    dim3 ggrid(F_SZ / 64, B_SZ / 64, SPLITK);   // (16, 8, 4) = 512 CTAs
    const int rgrid = B_SZ * F_SZ / 4 / 256;    // 512 blocks

    // 1. q = z @ Wq^T + bq
    sgemm_splitk<true><<<ggrid, 256>>>(z, Wq, part);
    reduce_k<true><<<rgrid, 256>>>(part, bq, q);
    // 2. qk = q @ Wk
    sgemm_splitk<false><<<ggrid, 256>>>(q, Wk, part);
    reduce_k<false><<<rgrid, 256>>>(part, nullptr, qkp);
    // 3. fused scores + softmax + weighted-input accumulation
    attn_stream<<<B_SZ, 256>>>(x, qkp, ctxf);
    // 4. out = ctxf @ Wv^T + bv
    sgemm_splitk<true><<<ggrid, 256>>>(ctxf, Wv, part);
    reduce_k<true><<<rgrid, 256>>>(part, bv, out);
}

// round 5
// speedup vs baseline: 1.3683x; 1.0420x over previous
#include <cuda_runtime.h>
#include <math.h>

#define B_SZ 512
#define T_SZ 256
#define F_SZ 1024
#define SPLITK 4
#define KSLICE (F_SZ / SPLITK)   // 256
#define BK 32
#define NTILES (KSLICE / BK)     // 8
#define THALF (T_SZ / 2)         // 128

// Scratch (allocation-free rule: __device__ globals)
__device__ float  g_q[B_SZ * F_SZ];
__device__ float  g_ctxf[B_SZ * F_SZ];
__device__ float  g_part[SPLITK * B_SZ * F_SZ];
__device__ float  g_pacc[2 * B_SZ * F_SZ];
__device__ float2 g_pmz[2 * B_SZ];

typedef unsigned long long u64;

__device__ __forceinline__ u64 pack_dup(float a) {
    u64 r;
    unsigned int ai = __float_as_uint(a);
    asm("mov.b64 %0, {%1, %1};" : "=l"(r) : "r"(ai));
    return r;
}
__device__ __forceinline__ void ffma2(u64& d, u64 a, u64 b) {
    asm("fma.rn.f32x2 %0, %1, %2, %0;" : "+l"(d) : "l"(a), "l"(b));
}
__device__ __forceinline__ float2 u64_f2(u64 v) {
    float2 f;
    f.x = __uint_as_float((unsigned int)v);
    f.y = __uint_as_float((unsigned int)(v >> 32));
    return f;
}

// ---------------------------------------------------------------------------
// Split-K SGEMM, M=512, N=1024, K=1024 hardcoded. 64x64 tile, BK=32,
// 256 threads, 4x4 micro-tile via fp32x2 FMA, double-buffered SMEM.
// B_IS_NT: B is [N,K] row-major (C = A @ B^T). else B is [K,N] (C = A @ B).
// ---------------------------------------------------------------------------
template <bool B_IS_NT>
__global__ __launch_bounds__(256, 3) void sgemm_splitk(const float* __restrict__ A,
                                                       const float* __restrict__ Bm,
                                                       float* __restrict__ Cpart)
{
    __shared__ float As[2][BK][64];
    __shared__ float Bs[2][BK][64];

    const int bm = blockIdx.y * 64;
    const int bn = blockIdx.x * 64;
    const int s  = blockIdx.z;
    const int k0 = s * KSLICE;
    const int tid = threadIdx.x;
    const int lrow = tid >> 2;            // 0..63   (NT-style loads)
    const int lk   = (tid & 3) * 4;       // 0,4,8,12
    const int krow = tid >> 3;            // 0..31   (NN B loads)
    const int nq   = (tid & 7) * 4;       // 0..28
    const int ty = tid >> 4;              // 0..15
    const int tx = tid & 15;              // 0..15

    const float* Ap = A + (size_t)(bm + lrow) * F_SZ + k0 + lk;
    const float* Bp = B_IS_NT ? Bm + (size_t)(bn + lrow) * F_SZ + k0 + lk
                              : Bm + (size_t)(k0 + krow) * F_SZ + bn + nq;

    float4 ra0 = *(const float4*)Ap;
    float4 ra1 = *(const float4*)(Ap + 16);
    float4 rb0, rb1;
    if (B_IS_NT) { rb0 = *(const float4*)Bp; rb1 = *(const float4*)(Bp + 16); }
    else         { rb0 = *(const float4*)Bp; rb1 = *(const float4*)(Bp + 32); }

    u64 acc[4][2];
    #pragma unroll
    for (int i = 0; i < 4; i++) { acc[i][0] = 0ull; acc[i][1] = 0ull; }

    // stage tile 0
    #pragma unroll
    for (int j = 0; j < 4; j++) {
        (&As[0][lk + 0][lrow])[j * 64]      = (&ra0.x)[j];
        (&As[0][lk + 16][lrow])[j * 64]     = (&ra1.x)[j];
    }
    if (B_IS_NT) {
        #pragma unroll
        for (int j = 0; j < 4; j++) {
            (&Bs[0][lk + 0][lrow])[j * 64]  = (&rb0.x)[j];
            (&Bs[0][lk + 16][lrow])[j * 64] = (&rb1.x)[j];
        }
    } else {
        *(float4*)&Bs[0][krow][nq]      = rb0;
        *(float4*)&Bs[0][krow][nq + 32] = rb1;
    }
    __syncthreads();

    int buf = 0;
    for (int kt = 0; kt < NTILES; kt++) {
        if (kt + 1 < NTILES) {                       // prefetch next tile
            ra0 = *(const float4*)(Ap + (kt + 1) * BK);
            ra1 = *(const float4*)(Ap + (kt + 1) * BK + 16);
            if (B_IS_NT) {
                rb0 = *(const float4*)(Bp + (kt + 1) * BK);
                rb1 = *(const float4*)(Bp + (kt + 1) * BK + 16);
            } else {
                rb0 = *(const float4*)(Bp + (size_t)(kt + 1) * BK * F_SZ);
                rb1 = *(const float4*)(Bp + (size_t)(kt + 1) * BK * F_SZ + 32);
            }
        }

        #pragma unroll
        for (int kk = 0; kk < BK; kk++) {
            float4 av = *(const float4*)&As[buf][kk][ty * 4];
            ulonglong2 bv = *(const ulonglong2*)&Bs[buf][kk][tx * 4];
            u64 a0 = pack_dup(av.x), a1 = pack_dup(av.y);
            u64 a2 = pack_dup(av.z), a3 = pack_dup(av.w);
            ffma2(acc[0][0], a0, bv.x); ffma2(acc[0][1], a0, bv.y);
            ffma2(acc[1][0], a1, bv.x); ffma2(acc[1][1], a1, bv.y);
            ffma2(acc[2][0], a2, bv.x); ffma2(acc[2][1], a2, bv.y);
            ffma2(acc[3][0], a3, bv.x); ffma2(acc[3][1], a3, bv.y);
        }

        if (kt + 1 < NTILES) {
            int nb = buf ^ 1;
            #pragma unroll
            for (int j = 0; j < 4; j++) {
                (&As[nb][lk + 0][lrow])[j * 64]      = (&ra0.x)[j];
                (&As[nb][lk + 16][lrow])[j * 64]     = (&ra1.x)[j];
            }
            if (B_IS_NT) {
                #pragma unroll
                for (int j = 0; j < 4; j++) {
                    (&Bs[nb][lk + 0][lrow])[j * 64]  = (&rb0.x)[j];
                    (&Bs[nb][lk + 16][lrow])[j * 64] = (&rb1.x)[j];
                }
            } else {
                *(float4*)&Bs[nb][krow][nq]      = rb0;
                *(float4*)&Bs[nb][krow][nq + 32] = rb1;
            }
            __syncthreads();
            buf = nb;
        }
    }

    float* Cp = Cpart + (size_t)s * (B_SZ * F_SZ)
                      + (size_t)(bm + ty * 4) * F_SZ + bn + tx * 4;
    #pragma unroll
    for (int i = 0; i < 4; i++) {
        float2 p0 = u64_f2(acc[i][0]);
        float2 p1 = u64_f2(acc[i][1]);
        float4 o = make_float4(p0.x, p0.y, p1.x, p1.y);
        *(float4*)(Cp + (size_t)i * F_SZ) = o;
    }
}

// ---------------------------------------------------------------------------
// Reduce SPLITK partials (+ bias broadcast over rows).
// ---------------------------------------------------------------------------
template <bool HAS_BIAS>
__global__ __launch_bounds__(256) void reduce_k(const float* __restrict__ part,
                                                const float* __restrict__ bias,
                                                float* __restrict__ out)
{
    const int idx = blockIdx.x * 256 + threadIdx.x;      // float4 index
    const int Q = B_SZ * F_SZ / 4;
    const float4* p = (const float4*)part;
    float4 a = p[idx];
    float4 b = p[idx + Q];
    float4 c = p[idx + 2 * Q];
    float4 d = p[idx + 3 * Q];
    float4 o;
    o.x = (a.x + b.x) + (c.x + d.x);
    o.y = (a.y + b.y) + (c.y + d.y);
    o.z = (a.z + b.z) + (c.z + d.z);
    o.w = (a.w + b.w) + (c.w + d.w);
    if (HAS_BIAS) {
        float4 bb = ((const float4*)bias)[idx & (F_SZ / 4 - 1)];
        o.x += bb.x; o.y += bb.y; o.z += bb.z; o.w += bb.w;
    }
    ((float4*)out)[idx] = o;
}

// ---------------------------------------------------------------------------
// Attention partial: grid (B, 2). CTA (b,h) handles T-rows [h*128, h*128+128).
// Sums the 4 split-K qk partials in the prologue (kills one reduce kernel).
// Emits unnormalized acc (at local max m), plus (m, Z).
// ---------------------------------------------------------------------------
__global__ __launch_bounds__(256) void attn_part(const float* __restrict__ x,
                                                 const float* __restrict__ qkpart,
                                                 float* __restrict__ pacc,
                                                 float2* __restrict__ pmz)
{
    const int b = blockIdx.x;
    const int h = blockIdx.y;
    const int tid = threadIdx.x;
    const int w = tid >> 5;
    const int l = tid & 31;

    __shared__ float4 qk4s[256];       // 4 KB
    __shared__ float4 tile[8 * 256];   // 32 KB
    __shared__ float  s_tile[8];

    {   // qk[b,:] = sum of 4 split-K partials (L2-resident, cheap)
        const int Q = B_SZ * F_SZ / 4;
        const int idx = b * 256 + tid;
        const float4* p = (const float4*)qkpart;
        float4 a = p[idx], bb = p[idx + Q], c = p[idx + 2 * Q], d = p[idx + 3 * Q];
        qk4s[tid] = make_float4((a.x + bb.x) + (c.x + d.x),
                                (a.y + bb.y) + (c.y + d.y),
                                (a.z + bb.z) + (c.z + d.z),
                                (a.w + bb.w) + (c.w + d.w));
    }

    const float4* x4 = (const float4*)(x + (size_t)b * T_SZ * F_SZ
                                         + (size_t)h * THALF * F_SZ);

    float4 r[8];
    #pragma unroll
    for (int i = 0; i < 8; i++) r[i] = x4[(size_t)i * 256 + tid];

    float m = -INFINITY, Z = 0.0f;
    float4 acc = make_float4(0.f, 0.f, 0.f, 0.f);

    for (int t0 = 0; t0 < THALF; t0 += 8) {
        __syncthreads();

        #pragma unroll
        for (int i = 0; i < 8; i++) tile[i * 256 + tid] = r[i];
        __syncthreads();

        if (t0 + 8 < THALF) {
            #pragma unroll
            for (int i = 0; i < 8; i++)
                r[i] = x4[(size_t)(t0 + 8 + i) * 256 + tid];
        }

        {   // scores: warp w -> dot(x[t0+w,:], qk)
            float p = 0.f;
            #pragma unroll
            for (int k = 0; k < 8; k++) {
                float4 xv = tile[w * 256 + l + 32 * k];
                float4 qv = qk4s[l + 32 * k];
                p += xv.x * qv.x + xv.y * qv.y + xv.z * qv.z + xv.w * qv.w;
            }
            #pragma unroll
            for (int off = 16; off; off >>= 1)
                p += __shfl_down_sync(0xffffffffu, p, off);
            if (l == 0) s_tile[w] = p;
        }
        __syncthreads();

        float tm = s_tile[0];
        #pragma unroll
        for (int t = 1; t < 8; t++) tm = fmaxf(tm, s_tile[t]);
        float m_new = fmaxf(m, tm);
        float scale = __expf(m - m_new);
        Z *= scale;
        acc.x *= scale; acc.y *= scale; acc.z *= scale; acc.w *= scale;

        #pragma unroll
        for (int t = 0; t < 8; t++) {
            float wt = __expf(s_tile[t] - m_new);
            Z += wt;
            float4 xv = tile[t * 256 + tid];
            acc.x += wt * xv.x; acc.y += wt * xv.y;
            acc.z += wt * xv.z; acc.w += wt * xv.w;
        }
        m = m_new;
    }

    ((float4*)pacc)[(size_t)(b * 2 + h) * 256 + tid] = acc;
    if (tid == 0) pmz[b * 2 + h] = make_float2(m, Z);
}

// ---------------------------------------------------------------------------
// Combine the two T-halves (flash-attention merge), normalize -> ctxf.
// ---------------------------------------------------------------------------
__global__ __launch_bounds__(256) void attn_combine(const float* __restrict__ pacc,
                                                    const float2* __restrict__ pmz,
                                                    float* __restrict__ ctxf)
{
    const int b = blockIdx.x;
    const int tid = threadIdx.x;
    float2 mz0 = pmz[2 * b];
    float2 mz1 = pmz[2 * b + 1];
    float m = fmaxf(mz0.x, mz1.x);
    float s0 = __expf(mz0.x - m);
    float s1 = __expf(mz1.x - m);
    float inv = 1.0f / (mz0.y * s0 + mz1.y * s1);

    float4 a0 = ((const float4*)pacc)[(size_t)(2 * b) * 256 + tid];
    float4 a1 = ((const float4*)pacc)[(size_t)(2 * b + 1) * 256 + tid];
    float4 o;
    o.x = (a0.x * s0 + a1.x * s1) * inv;
    o.y = (a0.y * s0 + a1.y * s1) * inv;
    o.z = (a0.z * s0 + a1.z * s1) * inv;
    o.w = (a0.w * s0 + a1.w * s1) * inv;
    ((float4*)(ctxf + (size_t)b * F_SZ))[tid] = o;
}

// ---------------------------------------------------------------------------
extern "C" void kernel_launch(void* const* d_in, const int* in_sizes, int n_in,
                              void* d_out, int out_size)
{
    const float* z  = (const float*)d_in[0];   // [B,F]
    const float* x  = (const float*)d_in[1];   // [B,T,F]
    const float* Wq = (const float*)d_in[2];   // [D,F]
    const float* Wk = (const float*)d_in[3];   // [D,F]
    const float* Wv = (const float*)d_in[4];   // [D,F]
    const float* bq = (const float*)d_in[5];   // [D]
    // d_in[6] = bk: softmax-invariant (constant shift per row) -> dropped
    const float* bv = (const float*)d_in[7];   // [D]
    float* out = (float*)d_out;                // [B,D]

    float *q, *ctxf, *part, *pacc;
    float2* pmz;
    cudaGetSymbolAddress((void**)&q,    g_q);
    cudaGetSymbolAddress((void**)&ctxf, g_ctxf);
    cudaGetSymbolAddress((void**)&part, g_part);
    cudaGetSymbolAddress((void**)&pacc, g_pacc);
    cudaGetSymbolAddress((void**)&pmz,  g_pmz);

    dim3 ggrid(F_SZ / 64, B_SZ / 64, SPLITK);   // (16, 8, 4) = 512 CTAs
    const int rgrid = B_SZ * F_SZ / 4 / 256;    // 512 blocks

    // 1. q = z @ Wq^T + bq
    sgemm_splitk<true><<<ggrid, 256>>>(z, Wq, part);
    reduce_k<true><<<rgrid, 256>>>(part, bq, q);
    // 2. qk = q @ Wk   (partials consumed directly by attn_part)
    sgemm_splitk<false><<<ggrid, 256>>>(q, Wk, part);
    // 3. fused scores + softmax + weighted-input accumulation, T split in 2
    attn_part<<<dim3(B_SZ, 2), 256>>>(x, part, pacc, pmz);
    attn_combine<<<B_SZ, 256>>>(pacc, pmz, ctxf);
    // 4. out = ctxf @ Wv^T + bv
    sgemm_splitk<true><<<ggrid, 256>>>(ctxf, Wv, part);
    reduce_k<true><<<rgrid, 256>>>(part, bv, out);
}

// round 7
// speedup vs baseline: 1.4590x; 1.0663x over previous
#include <cuda_runtime.h>
#include <math.h>

#define B_SZ 512
#define T_SZ 256
#define F_SZ 1024
#define SPLITK 4
#define KSLICE (F_SZ / SPLITK)   // 256
#define BK 32
#define NTILES (KSLICE / BK)     // 8
#define TSPLIT 4
#define TCH (T_SZ / TSPLIT)      // 64
#define NIT (TCH / 8)            // 8

// Scratch (allocation-free rule: __device__ globals)
__device__ float  g_q[B_SZ * F_SZ];
__device__ float  g_ctxf[B_SZ * F_SZ];
__device__ float  g_part[SPLITK * B_SZ * F_SZ];
__device__ float  g_pacc[TSPLIT * B_SZ * F_SZ];
__device__ float2 g_pmz[TSPLIT * B_SZ];

typedef unsigned long long u64;

__device__ __forceinline__ u64 pack_dup(float a) {
    u64 r;
    unsigned int ai = __float_as_uint(a);
    asm("mov.b64 %0, {%1, %1};" : "=l"(r) : "r"(ai));
    return r;
}
__device__ __forceinline__ void ffma2(u64& d, u64 a, u64 b) {
    asm("fma.rn.f32x2 %0, %1, %2, %0;" : "+l"(d) : "l"(a), "l"(b));
}
__device__ __forceinline__ float2 u64_f2(u64 v) {
    float2 f;
    f.x = __uint_as_float((unsigned int)v);
    f.y = __uint_as_float((unsigned int)(v >> 32));
    return f;
}

// ---------------------------------------------------------------------------
// Split-K SGEMM, M=512, N=1024, K=1024. 64x64 tile, BK=32, 256 threads,
// 4x4 micro-tile via fp32x2 FMA, double-buffered SMEM.
// occ target 4 CTAs/SM -> grid 512 fits in ONE wave (n_conc=592).
// ---------------------------------------------------------------------------
template <bool B_IS_NT>
__global__ __launch_bounds__(256, 4) void sgemm_splitk(const float* __restrict__ A,
                                                       const float* __restrict__ Bm,
                                                       float* __restrict__ Cpart)
{
    __shared__ float As[2][BK][64];
    __shared__ float Bs[2][BK][64];

    const int bm = blockIdx.y * 64;
    const int bn = blockIdx.x * 64;
    const int s  = blockIdx.z;
    const int k0 = s * KSLICE;
    const int tid = threadIdx.x;
    const int lrow = tid >> 2;            // 0..63   (NT-style loads)
    const int lk   = (tid & 3) * 4;       // 0,4,8,12
    const int krow = tid >> 3;            // 0..31   (NN B loads)
    const int nq   = (tid & 7) * 4;       // 0..28
    const int ty = tid >> 4;              // 0..15
    const int tx = tid & 15;              // 0..15

    const float* Ap = A + (size_t)(bm + lrow) * F_SZ + k0 + lk;
    const float* Bp = B_IS_NT ? Bm + (size_t)(bn + lrow) * F_SZ + k0 + lk
                              : Bm + (size_t)(k0 + krow) * F_SZ + bn + nq;

    float4 ra0 = *(const float4*)Ap;
    float4 ra1 = *(const float4*)(Ap + 16);
    float4 rb0, rb1;
    if (B_IS_NT) { rb0 = *(const float4*)Bp; rb1 = *(const float4*)(Bp + 16); }
    else         { rb0 = *(const float4*)Bp; rb1 = *(const float4*)(Bp + 32); }

    u64 acc[4][2];
    #pragma unroll
    for (int i = 0; i < 4; i++) { acc[i][0] = 0ull; acc[i][1] = 0ull; }

    // stage tile 0
    #pragma unroll
    for (int j = 0; j < 4; j++) {
        (&As[0][lk + 0][lrow])[j * 64]      = (&ra0.x)[j];
        (&As[0][lk + 16][lrow])[j * 64]     = (&ra1.x)[j];
    }
    if (B_IS_NT) {
        #pragma unroll
        for (int j = 0; j < 4; j++) {
            (&Bs[0][lk + 0][lrow])[j * 64]  = (&rb0.x)[j];
            (&Bs[0][lk + 16][lrow])[j * 64] = (&rb1.x)[j];
        }
    } else {
        *(float4*)&Bs[0][krow][nq]      = rb0;
        *(float4*)&Bs[0][krow][nq + 32] = rb1;
    }
    __syncthreads();

    int buf = 0;
    for (int kt = 0; kt < NTILES; kt++) {
        if (kt + 1 < NTILES) {                       // prefetch next tile
            ra0 = *(const float4*)(Ap + (kt + 1) * BK);
            ra1 = *(const float4*)(Ap + (kt + 1) * BK + 16);
            if (B_IS_NT) {
                rb0 = *(const float4*)(Bp + (kt + 1) * BK);
                rb1 = *(const float4*)(Bp + (kt + 1) * BK + 16);
            } else {
                rb0 = *(const float4*)(Bp + (size_t)(kt + 1) * BK * F_SZ);
                rb1 = *(const float4*)(Bp + (size_t)(kt + 1) * BK * F_SZ + 32);
            }
        }

        #pragma unroll
        for (int kk = 0; kk < BK; kk++) {
            float4 av = *(const float4*)&As[buf][kk][ty * 4];
            ulonglong2 bv = *(const ulonglong2*)&Bs[buf][kk][tx * 4];
            u64 a0 = pack_dup(av.x), a1 = pack_dup(av.y);
            u64 a2 = pack_dup(av.z), a3 = pack_dup(av.w);
            ffma2(acc[0][0], a0, bv.x); ffma2(acc[0][1], a0, bv.y);
            ffma2(acc[1][0], a1, bv.x); ffma2(acc[1][1], a1, bv.y);
            ffma2(acc[2][0], a2, bv.x); ffma2(acc[2][1], a2, bv.y);
            ffma2(acc[3][0], a3, bv.x); ffma2(acc[3][1], a3, bv.y);
        }

        if (kt + 1 < NTILES) {
            int nb = buf ^ 1;
            #pragma unroll
            for (int j = 0; j < 4; j++) {
                (&As[nb][lk + 0][lrow])[j * 64]      = (&ra0.x)[j];
                (&As[nb][lk + 16][lrow])[j * 64]     = (&ra1.x)[j];
            }
            if (B_IS_NT) {
                #pragma unroll
                for (int j = 0; j < 4; j++) {
                    (&Bs[nb][lk + 0][lrow])[j * 64]  = (&rb0.x)[j];
                    (&Bs[nb][lk + 16][lrow])[j * 64] = (&rb1.x)[j];
                }
            } else {
                *(float4*)&Bs[nb][krow][nq]      = rb0;
                *(float4*)&Bs[nb][krow][nq + 32] = rb1;
            }
            __syncthreads();
            buf = nb;
        }
    }

    float* Cp = Cpart + (size_t)s * (B_SZ * F_SZ)
                      + (size_t)(bm + ty * 4) * F_SZ + bn + tx * 4;
    #pragma unroll
    for (int i = 0; i < 4; i++) {
        float2 p0 = u64_f2(acc[i][0]);
        float2 p1 = u64_f2(acc[i][1]);
        float4 o = make_float4(p0.x, p0.y, p1.x, p1.y);
        *(float4*)(Cp + (size_t)i * F_SZ) = o;
    }
}

// ---------------------------------------------------------------------------
// Reduce SPLITK partials (+ bias broadcast over rows).
// ---------------------------------------------------------------------------
template <bool HAS_BIAS>
__global__ __launch_bounds__(256) void reduce_k(const float* __restrict__ part,
                                                const float* __restrict__ bias,
                                                float* __restrict__ out)
{
    const int idx = blockIdx.x * 256 + threadIdx.x;      // float4 index
    const int Q = B_SZ * F_SZ / 4;
    const float4* p = (const float4*)part;
    float4 a = p[idx];
    float4 b = p[idx + Q];
    float4 c = p[idx + 2 * Q];
    float4 d = p[idx + 3 * Q];
    float4 o;
    o.x = (a.x + b.x) + (c.x + d.x);
    o.y = (a.y + b.y) + (c.y + d.y);
    o.z = (a.z + b.z) + (c.z + d.z);
    o.w = (a.w + b.w) + (c.w + d.w);
    if (HAS_BIAS) {
        float4 bb = ((const float4*)bias)[idx & (F_SZ / 4 - 1)];
        o.x += bb.x; o.y += bb.y; o.z += bb.z; o.w += bb.w;
    }
    ((float4*)out)[idx] = o;
}

// ---------------------------------------------------------------------------
// Attention partial, fully register-resident: grid (B, TSPLIT).
// Each thread owns 4 f-columns of 8 T-rows in registers. Partial scores go
// through a small red[8][256] buffer (2 syncs/tile); accumulation is pure
// register FMA. Next tile's loads are in flight across the score phase.
// ---------------------------------------------------------------------------
__global__ __launch_bounds__(256, 2) void attn_part(const float* __restrict__ x,
                                                    const float* __restrict__ qkpart,
                                                    float* __restrict__ pacc,
                                                    float2* __restrict__ pmz)
{
    const int b = blockIdx.x;
    const int h = blockIdx.y;
    const int tid = threadIdx.x;
    const int w = tid >> 5;
    const int l = tid & 31;

    __shared__ float red[8][256];      // 8 KB
    __shared__ float s_tile[8];

    // qk[b, 4*tid .. 4*tid+3] = sum of 4 split-K partials -> registers
    float4 qk;
    {
        const int Q = B_SZ * F_SZ / 4;
        const int idx = b * 256 + tid;
        const float4* p = (const float4*)qkpart;
        float4 a = p[idx], bb = p[idx + Q], c = p[idx + 2 * Q], d = p[idx + 3 * Q];
        qk = make_float4((a.x + bb.x) + (c.x + d.x),
                         (a.y + bb.y) + (c.y + d.y),
                         (a.z + bb.z) + (c.z + d.z),
                         (a.w + bb.w) + (c.w + d.w));
    }

    const float4* x4 = (const float4*)(x + (size_t)b * T_SZ * F_SZ
                                         + (size_t)h * TCH * F_SZ);

    float4 cur[8], nxt[8];
    #pragma unroll
    for (int i = 0; i < 8; i++) cur[i] = x4[(size_t)i * 256 + tid];

    float m = -INFINITY, Z = 0.0f;
    float4 acc = make_float4(0.f, 0.f, 0.f, 0.f);

    #pragma unroll
    for (int it = 0; it < NIT; it++) {
        if (it + 1 < NIT) {            // next tile LDGs in flight over scores
            #pragma unroll
            for (int i = 0; i < 8; i++)
                nxt[i] = x4[(size_t)((it + 1) * 8 + i) * 256 + tid];
        }

        // partial scores from registers -> red
        #pragma unroll
        for (int i = 0; i < 8; i++) {
            float4 xv = cur[i];
            red[i][tid] = xv.x * qk.x + xv.y * qk.y + xv.z * qk.z + xv.w * qk.w;
        }
        __syncthreads();

        // warp w reduces row w (256 partials, conflict-free)
        {
            float s = 0.f;
            #pragma unroll
            for (int j = 0; j < 8; j++) s += red[w][l + 32 * j];
            #pragma unroll
            for (int off = 16; off; off >>= 1)
                s += __shfl_down_sync(0xffffffffu, s, off);
            if (l == 0) s_tile[w] = s;
        }
        __syncthreads();

        // online softmax + register accumulation
        float tm = s_tile[0];
        #pragma unroll
        for (int t = 1; t < 8; t++) tm = fmaxf(tm, s_tile[t]);
        float m_new = fmaxf(m, tm);
        float scale = __expf(m - m_new);
        Z *= scale;
        acc.x *= scale; acc.y *= scale; acc.z *= scale; acc.w *= scale;

        #pragma unroll
        for (int t = 0; t < 8; t++) {
            float wt = __expf(s_tile[t] - m_new);
            Z += wt;
            float4 xv = cur[t];
            acc.x += wt * xv.x; acc.y += wt * xv.y;
            acc.z += wt * xv.z; acc.w += wt * xv.w;
        }
        m = m_new;

        if (it + 1 < NIT) {
            #pragma unroll
            for (int i = 0; i < 8; i++) cur[i] = nxt[i];
        }
    }

    ((float4*)pacc)[(size_t)(b * TSPLIT + h) * 256 + tid] = acc;
    if (tid == 0) pmz[b * TSPLIT + h] = make_float2(m, Z);
}

// ---------------------------------------------------------------------------
// Combine the TSPLIT T-chunks (flash merge), normalize -> ctxf.
// ---------------------------------------------------------------------------
__global__ __launch_bounds__(256) void attn_combine(const float* __restrict__ pacc,
                                                    const float2* __restrict__ pmz,
                                                    float* __restrict__ ctxf)
{
    const int b = blockIdx.x;
    const int tid = threadIdx.x;

    float2 mz[TSPLIT];
    #pragma unroll
    for (int i = 0; i < TSPLIT; i++) mz[i] = pmz[TSPLIT * b + i];
    float m = mz[0].x;
    #pragma unroll
    for (int i = 1; i < TSPLIT; i++) m = fmaxf(m, mz[i].x);

    float sc[TSPLIT];
    float Z = 0.f;
    #pragma unroll
    for (int i = 0; i < TSPLIT; i++) { sc[i] = __expf(mz[i].x - m); Z += mz[i].y * sc[i]; }
    float inv = 1.0f / Z;

    float4 o = make_float4(0.f, 0.f, 0.f, 0.f);
    #pragma unroll
    for (int i = 0; i < TSPLIT; i++) {
        float4 a = ((const float4*)pacc)[(size_t)(TSPLIT * b + i) * 256 + tid];
        o.x += a.x * sc[i]; o.y += a.y * sc[i];
        o.z += a.z * sc[i]; o.w += a.w * sc[i];
    }
    o.x *= inv; o.y *= inv; o.z *= inv; o.w *= inv;
    ((float4*)(ctxf + (size_t)b * F_SZ))[tid] = o;
}

// ---------------------------------------------------------------------------
extern "C" void kernel_launch(void* const* d_in, const int* in_sizes, int n_in,
                              void* d_out, int out_size)
{
    const float* z  = (const float*)d_in[0];   // [B,F]
    const float* x  = (const float*)d_in[1];   // [B,T,F]
    const float* Wq = (const float*)d_in[2];   // [D,F]
    const float* Wk = (const float*)d_in[3];   // [D,F]
    const float* Wv = (const float*)d_in[4];   // [D,F]
    const float* bq = (const float*)d_in[5];   // [D]
    // d_in[6] = bk: softmax-invariant (constant shift per row) -> dropped
    const float* bv = (const float*)d_in[7];   // [D]
    float* out = (float*)d_out;                // [B,D]

    float *q, *ctxf, *part, *pacc;
    float2* pmz;
    cudaGetSymbolAddress((void**)&q,    g_q);
    cudaGetSymbolAddress((void**)&ctxf, g_ctxf);
    cudaGetSymbolAddress((void**)&part, g_part);
    cudaGetSymbolAddress((void**)&pacc, g_pacc);
    cudaGetSymbolAddress((void**)&pmz,  g_pmz);

    dim3 ggrid(F_SZ / 64, B_SZ / 64, SPLITK);   // (16, 8, 4) = 512 CTAs
    const int rgrid = B_SZ * F_SZ / 4 / 256;    // 512 blocks

    // 1. q = z @ Wq^T + bq
    sgemm_splitk<true><<<ggrid, 256>>>(z, Wq, part);
    reduce_k<true><<<rgrid, 256>>>(part, bq, q);
    // 2. qk = q @ Wk   (partials consumed directly by attn_part)
    sgemm_splitk<false><<<ggrid, 256>>>(q, Wk, part);
    // 3. fused scores + softmax + weighted-input accumulation, T split in 4
    attn_part<<<dim3(B_SZ, TSPLIT), 256>>>(x, part, pacc, pmz);
    attn_combine<<<B_SZ, 256>>>(pacc, pmz, ctxf);
    // 4. out = ctxf @ Wv^T + bv
    sgemm_splitk<true><<<ggrid, 256>>>(ctxf, Wv, part);
    reduce_k<true><<<rgrid, 256>>>(part, bv, out);
}